// round 15
// baseline (speedup 1.0000x reference)
#include <cuda_runtime.h>

// Dis_model_60129542275: bilinear flow-warp resample.
// source [16,768,1024,4] f32, flow [16,768,1024,2] f32 (dy,dx), out [16,768,1024,4] f32.
//
// R14 (converged config, final geometry experiment): the measured-optimum
// structure —
//  - lane-pair cooperative column gathers: even lane loads the LEFT bilinear
//    column, odd lane the RIGHT, of BOTH pixels of its lane pair; each gather
//    instruction's pair addresses are 16B apart -> one 128B L1 wavefront with
//    p=7/8. Gather floor: 2.25 wavefronts/pixel (provably minimal for any
//    lane assignment; y-taps are 4KB apart, cross-pixel tap collisions have
//    negligible probability). L1TEX wavefront throughput is the binding
//    resource; duty is pattern-capped at ~85%.
//  - flow read as one broadcast float4 per lane pair; zero metadata shuffles.
//  - 2 pixels/thread; 4 result shfls per pixel; natural register allocation.
//  - gathers via ld.global.cg; stores via st.global.cs (streaming).
//  - (b, y) decoded once per thread (block never crosses a row boundary).
// R14 change: THREADS 256 -> 512, so each CTA covers EXACTLY one image row
// (1024 px): contiguous full-width gather band per CTA, half the CTA count,
// identical per-thread code. Everything else byte-identical to R13.
// Measured-worse neighborhood: PPT=3 +9us, forced 64-reg +12us, OOB->line0
// redirect +73us, no lane pairing +30us.

static constexpr int Bn = 16;
static constexpr int Hn = 768;
static constexpr int Wn = 1024;
static constexpr int HW = Hn * Wn;
static constexpr int NPIX = Bn * HW;
static constexpr int THREADS = 512;
static constexpr int PIX_PER_BLOCK = 2 * THREADS;   // 1024 = one full row

__device__ __forceinline__ float4 ldg_cg4(const float4* p) {
    float4 v;
    asm("ld.global.cg.v4.f32 {%0,%1,%2,%3}, [%4];"
        : "=f"(v.x), "=f"(v.y), "=f"(v.z), "=f"(v.w)
        : "l"(p));
    return v;
}

__device__ __forceinline__ void stg_cs4(float4* p, float4 v) {
    asm volatile("st.global.cs.v4.f32 [%0], {%1,%2,%3,%4};"
                 :: "l"(p), "f"(v.x), "f"(v.y), "f"(v.z), "f"(v.w)
                 : "memory");
}

struct Meta { int off0, off1; float g0, g1; };

// Per-pixel, per-column metadata given precomputed pixel coords. xsel = x0 for
// even lanes, x1 for odd lanes. Clamped coords make the loads always-safe;
// zero (masked) weights kill any clamped/OOB contribution exactly.
__device__ __forceinline__ Meta setup_px(float xf, float yf, int rowbase,
                                         float dy, float dx, bool even)
{
    const float wy = yf + dy;
    const float wx = xf + dx;

    const float m = ((wy >= 0.0f) & (wy <= (float)(Hn - 1)) &
                     (wx >= 0.0f) & (wx <= (float)(Wn - 1))) ? 1.0f : 0.0f;

    const float fy = floorf(wy);
    const float fx = floorf(wx);
    const float wrt = wx - fx;                     // right weight
    const float wdn = wy - fy;                     // down weight
    const float wcol = even ? (1.0f - wrt) : wrt;  // this lane's column weight
    const float wup = (1.0f - wdn) * m;
    const float wdm = wdn * m;

    const int x0 = min(max((int)fx, 0), Wn - 1);
    const int y0 = min(max((int)fy, 0), Hn - 1);
    const int xs = even ? x0 : min(x0 + 1, Wn - 1);
    const int y1 = min(y0 + 1, Hn - 1);

    Meta mt;
    const int base = rowbase + xs;
    mt.off0 = base + y0 * Wn;
    mt.off1 = base + y1 * Wn;
    mt.g0 = wcol * wup;
    mt.g1 = wcol * wdm;
    return mt;
}

__global__ __launch_bounds__(THREADS) void warp_bilinear_r14_kernel(
    const float4* __restrict__ src,    // [B*H*W] float4 (C=4)
    const float4* __restrict__ flow4,  // [B*H*W/2] float4 = 2 pixels' (dy,dx)
    float4* __restrict__ out)          // [B*H*W] float4
{
    const int tid = threadIdx.x;
    const bool even = ((tid & 1) == 0);
    const unsigned FULL = 0xffffffffu;
    const int p0 = blockIdx.x * PIX_PER_BLOCK + tid;

    // Decode ONCE: the block covers exactly one image row, so (b, y) are
    // shared by all 4 pixels this thread touches; x varies by +THREADS (j)
    // and +1 (pair parity).
    const int xA0 = p0 & (Wn - 1);
    const int r   = p0 >> 10;                       // Wn = 2^10
    const int b   = (int)((unsigned)r / (unsigned)Hn);
    const int y   = r - b * Hn;
    const float yf = (float)y;
    const int rowbase = b * HW;
    const float xAe = (float)(xA0 & ~1);            // x of pair pixel A (j=0)

    Meta mA[2], mB[2];

    #pragma unroll
    for (int j = 0; j < 2; ++j) {
        const int pA = (p0 & ~1) + j * THREADS;      // even pixel of the pair
        const float xa = xAe + (float)(j * THREADS); // its x coordinate
        // One float4 = (dyA, dxA, dyB, dxB); broadcast across the lane pair.
        const float4 f = __ldg(flow4 + (pA >> 1));
        mA[j] = setup_px(xa,        yf, rowbase, f.x, f.y, even);  // pixel A
        mB[j] = setup_px(xa + 1.0f, yf, rowbase, f.z, f.w, even);  // pixel B
    }

    // Issue all 8 gathers back-to-back via L1-bypassing .cg loads. Within each
    // instruction the lane pair's two addresses are 16B apart -> one 128B
    // wavefront with p=7/8.
    float4 TA0[2], TA1[2], TB0[2], TB1[2];
    #pragma unroll
    for (int j = 0; j < 2; ++j) {
        TA0[j] = ldg_cg4(src + mA[j].off0);
        TA1[j] = ldg_cg4(src + mA[j].off1);
        TB0[j] = ldg_cg4(src + mB[j].off0);
        TB1[j] = ldg_cg4(src + mB[j].off1);
    }

    #pragma unroll
    for (int j = 0; j < 2; ++j) {
        // This lane's column partial for each pair pixel.
        float4 pAc, pBc;
        pAc.x = TA0[j].x * mA[j].g0 + TA1[j].x * mA[j].g1;
        pAc.y = TA0[j].y * mA[j].g0 + TA1[j].y * mA[j].g1;
        pAc.z = TA0[j].z * mA[j].g0 + TA1[j].z * mA[j].g1;
        pAc.w = TA0[j].w * mA[j].g0 + TA1[j].w * mA[j].g1;
        pBc.x = TB0[j].x * mB[j].g0 + TB1[j].x * mB[j].g1;
        pBc.y = TB0[j].y * mB[j].g0 + TB1[j].y * mB[j].g1;
        pBc.z = TB0[j].z * mB[j].g0 + TB1[j].z * mB[j].g1;
        pBc.w = TB0[j].w * mB[j].g0 + TB1[j].w * mB[j].g1;

        // Exchange the partner pixel's partial; keep own pixel's.
        float4 sendv;
        sendv.x = even ? pBc.x : pAc.x;
        sendv.y = even ? pBc.y : pAc.y;
        sendv.z = even ? pBc.z : pAc.z;
        sendv.w = even ? pBc.w : pAc.w;

        float4 res;
        res.x = (even ? pAc.x : pBc.x) + __shfl_xor_sync(FULL, sendv.x, 1);
        res.y = (even ? pAc.y : pBc.y) + __shfl_xor_sync(FULL, sendv.y, 1);
        res.z = (even ? pAc.z : pBc.z) + __shfl_xor_sync(FULL, sendv.z, 1);
        res.w = (even ? pAc.w : pBc.w) + __shfl_xor_sync(FULL, sendv.w, 1);

        stg_cs4(out + (p0 + j * THREADS), res);   // streaming store, own pixel
    }
}

extern "C" void kernel_launch(void* const* d_in, const int* in_sizes, int n_in,
                              void* d_out, int out_size)
{
    const float4* src   = (const float4*)d_in[0];   // source [16,768,1024,4]
    const float4* flow4 = (const float4*)d_in[1];   // flow   [16,768,1024,2] as float4 pairs
    float4* out = (float4*)d_out;

    static_assert(NPIX % PIX_PER_BLOCK == 0, "exact grid");
    constexpr int blocks = NPIX / PIX_PER_BLOCK;    // 12288 (one row per block)
    warp_bilinear_r14_kernel<<<blocks, THREADS>>>(src, flow4, out);
}

// round 16
// speedup vs baseline: 1.0146x; 1.0146x over previous
#include <cuda_runtime.h>

// Dis_model_60129542275: bilinear flow-warp resample.  FINAL (converged).
// source [16,768,1024,4] f32, flow [16,768,1024,2] f32 (dy,dx), out [16,768,1024,4] f32.
//
// Converged configuration (R13; best measured 127.1-127.5us):
//  - lane-pair cooperative column gathers: even lane loads the LEFT bilinear
//    column, odd lane the RIGHT, of BOTH pixels of its lane pair; each gather
//    instruction's pair addresses are 16B apart -> one 128B L1 wavefront with
//    p=7/8. Gather floor: 2.25 wavefronts/pixel (provably minimal for any
//    lane-to-tap assignment: y-taps are 4KB apart, cross-pixel collisions
//    negligible). L1TEX wavefront throughput is the binding resource; duty is
//    pattern-capped at ~85% (invariant across occupancy 43-94%, MLP 4-12).
//  - flow read as one broadcast float4 per lane pair; zero metadata shuffles.
//  - 2 pixels/thread; 4 result shfls per pixel; natural register allocation.
//  - gathers via ld.global.cg; stores via st.global.cs (streaming).
//  - (b, y) decoded once per thread (block never crosses a row boundary).
// Measured-worse neighborhood: PPT=3 +9us, forced 64-reg +12us, OOB->line0
// redirect +73us, no lane pairing +30us; 512-thread row-aligned CTAs neutral.
// DRAM traffic is at the 503MB minimum; model 2.6 wf/px / 0.85 duty / 148 SM
// ~= 126us matches measurement — structural floor reached.

static constexpr int Bn = 16;
static constexpr int Hn = 768;
static constexpr int Wn = 1024;
static constexpr int HW = Hn * Wn;
static constexpr int NPIX = Bn * HW;
static constexpr int THREADS = 256;
static constexpr int PIX_PER_BLOCK = 2 * THREADS;   // 512

__device__ __forceinline__ float4 ldg_cg4(const float4* p) {
    float4 v;
    asm("ld.global.cg.v4.f32 {%0,%1,%2,%3}, [%4];"
        : "=f"(v.x), "=f"(v.y), "=f"(v.z), "=f"(v.w)
        : "l"(p));
    return v;
}

__device__ __forceinline__ void stg_cs4(float4* p, float4 v) {
    asm volatile("st.global.cs.v4.f32 [%0], {%1,%2,%3,%4};"
                 :: "l"(p), "f"(v.x), "f"(v.y), "f"(v.z), "f"(v.w)
                 : "memory");
}

struct Meta { int off0, off1; float g0, g1; };

// Per-pixel, per-column metadata given precomputed pixel coords. xsel = x0 for
// even lanes, x1 for odd lanes. Clamped coords make the loads always-safe;
// zero (masked) weights kill any clamped/OOB contribution exactly, matching
// the reference's safe-gather + mask semantics bit-for-bit.
__device__ __forceinline__ Meta setup_px(float xf, float yf, int rowbase,
                                         float dy, float dx, bool even)
{
    const float wy = yf + dy;
    const float wx = xf + dx;

    const float m = ((wy >= 0.0f) & (wy <= (float)(Hn - 1)) &
                     (wx >= 0.0f) & (wx <= (float)(Wn - 1))) ? 1.0f : 0.0f;

    const float fy = floorf(wy);
    const float fx = floorf(wx);
    const float wrt = wx - fx;                     // right weight
    const float wdn = wy - fy;                     // down weight
    const float wcol = even ? (1.0f - wrt) : wrt;  // this lane's column weight
    const float wup = (1.0f - wdn) * m;
    const float wdm = wdn * m;

    const int x0 = min(max((int)fx, 0), Wn - 1);
    const int y0 = min(max((int)fy, 0), Hn - 1);
    const int xs = even ? x0 : min(x0 + 1, Wn - 1);
    const int y1 = min(y0 + 1, Hn - 1);

    Meta mt;
    const int base = rowbase + xs;
    mt.off0 = base + y0 * Wn;
    mt.off1 = base + y1 * Wn;
    mt.g0 = wcol * wup;
    mt.g1 = wcol * wdm;
    return mt;
}

__global__ __launch_bounds__(THREADS) void warp_bilinear_final_kernel(
    const float4* __restrict__ src,    // [B*H*W] float4 (C=4)
    const float4* __restrict__ flow4,  // [B*H*W/2] float4 = 2 pixels' (dy,dx)
    float4* __restrict__ out)          // [B*H*W] float4
{
    const int tid = threadIdx.x;
    const bool even = ((tid & 1) == 0);
    const unsigned FULL = 0xffffffffu;
    const int p0 = blockIdx.x * PIX_PER_BLOCK + tid;

    // Decode ONCE: all 4 pixels this thread touches share (b, y); x varies by
    // +256 (j) and +1 (pair parity). Blocks are 512-aligned within 1024-px
    // rows, so a block never crosses a row boundary.
    const int xA0 = p0 & (Wn - 1);
    const int r   = p0 >> 10;                       // Wn = 2^10
    const int b   = (int)((unsigned)r / (unsigned)Hn);
    const int y   = r - b * Hn;
    const float yf = (float)y;
    const int rowbase = b * HW;
    const float xAe = (float)(xA0 & ~1);            // x of pair pixel A (j=0)

    Meta mA[2], mB[2];

    #pragma unroll
    for (int j = 0; j < 2; ++j) {
        const int pA = (p0 & ~1) + j * THREADS;      // even pixel of the pair
        const float xa = xAe + (float)(j * THREADS); // its x coordinate
        // One float4 = (dyA, dxA, dyB, dxB); broadcast across the lane pair.
        const float4 f = __ldg(flow4 + (pA >> 1));
        mA[j] = setup_px(xa,        yf, rowbase, f.x, f.y, even);  // pixel A
        mB[j] = setup_px(xa + 1.0f, yf, rowbase, f.z, f.w, even);  // pixel B
    }

    // Issue all 8 gathers back-to-back via L1-bypassing .cg loads. Within each
    // instruction the lane pair's two addresses are 16B apart -> one 128B
    // wavefront with p=7/8.
    float4 TA0[2], TA1[2], TB0[2], TB1[2];
    #pragma unroll
    for (int j = 0; j < 2; ++j) {
        TA0[j] = ldg_cg4(src + mA[j].off0);
        TA1[j] = ldg_cg4(src + mA[j].off1);
        TB0[j] = ldg_cg4(src + mB[j].off0);
        TB1[j] = ldg_cg4(src + mB[j].off1);
    }

    #pragma unroll
    for (int j = 0; j < 2; ++j) {
        // This lane's column partial for each pair pixel.
        float4 pAc, pBc;
        pAc.x = TA0[j].x * mA[j].g0 + TA1[j].x * mA[j].g1;
        pAc.y = TA0[j].y * mA[j].g0 + TA1[j].y * mA[j].g1;
        pAc.z = TA0[j].z * mA[j].g0 + TA1[j].z * mA[j].g1;
        pAc.w = TA0[j].w * mA[j].g0 + TA1[j].w * mA[j].g1;
        pBc.x = TB0[j].x * mB[j].g0 + TB1[j].x * mB[j].g1;
        pBc.y = TB0[j].y * mB[j].g0 + TB1[j].y * mB[j].g1;
        pBc.z = TB0[j].z * mB[j].g0 + TB1[j].z * mB[j].g1;
        pBc.w = TB0[j].w * mB[j].g0 + TB1[j].w * mB[j].g1;

        // Exchange the partner pixel's partial; keep own pixel's.
        float4 sendv;
        sendv.x = even ? pBc.x : pAc.x;
        sendv.y = even ? pBc.y : pAc.y;
        sendv.z = even ? pBc.z : pAc.z;
        sendv.w = even ? pBc.w : pAc.w;

        float4 res;
        res.x = (even ? pAc.x : pBc.x) + __shfl_xor_sync(FULL, sendv.x, 1);
        res.y = (even ? pAc.y : pBc.y) + __shfl_xor_sync(FULL, sendv.y, 1);
        res.z = (even ? pAc.z : pBc.z) + __shfl_xor_sync(FULL, sendv.z, 1);
        res.w = (even ? pAc.w : pBc.w) + __shfl_xor_sync(FULL, sendv.w, 1);

        stg_cs4(out + (p0 + j * THREADS), res);   // streaming store, own pixel
    }
}

extern "C" void kernel_launch(void* const* d_in, const int* in_sizes, int n_in,
                              void* d_out, int out_size)
{
    const float4* src   = (const float4*)d_in[0];   // source [16,768,1024,4]
    const float4* flow4 = (const float4*)d_in[1];   // flow   [16,768,1024,2] as float4 pairs
    float4* out = (float4*)d_out;

    static_assert(NPIX % PIX_PER_BLOCK == 0, "exact grid");
    constexpr int blocks = NPIX / PIX_PER_BLOCK;    // 24576
    warp_bilinear_final_kernel<<<blocks, THREADS>>>(src, flow4, out);
}